// round 13
// baseline (speedup 1.0000x reference)
#include <cuda_runtime.h>
#include <cstdint>

// Problem constants
#define B      32
#define T_IN   24
#define T_OUT  12
#define D      10
#define M      64
#define N      128
#define MN     (M * N)                 // 8192
#define IN_T_STRIDE  (D * MN)          // 81920 floats between t slices
#define IN_B_STRIDE  (T_IN * IN_T_STRIDE)
#define OUT_B_STRIDE (T_OUT * MN)
#define MU_    0.08f
#define LAM    0.92f

#define CHUNK      256                 // mn per CTA
#define NCHUNK     (MN / CHUNK)        // 32
#define THREADS    128                 // 2 series per thread (float2)
#define TILE_BYTES (T_IN * CHUNK * 4)  // 24 KB

struct __align__(128) Smem {
    float tile[T_IN][CHUNK];           // 24 KB in
    float outb[T_OUT][CHUNK];          // 12 KB out staging
    alignas(8) uint64_t mbar;
};

__device__ __forceinline__ uint32_t smem_u32(const void* p) {
    return (uint32_t)__cvta_generic_to_shared(p);
}

__global__ __launch_bounds__(THREADS)
void movavg_kernel(const float* __restrict__ x, float* __restrict__ out)
{
    __shared__ Smem sm;

    const int bid   = blockIdx.x;
    const int b     = bid >> 5;          // / NCHUNK
    const int chunk = bid & (NCHUNK - 1);
    const int tid   = threadIdx.x;

    const uint32_t mb = smem_u32(&sm.mbar);

    if (tid == 0) {
        asm volatile("mbarrier.init.shared::cta.b64 [%0], %1;" :: "r"(mb), "r"(1));
        asm volatile("mbarrier.arrive.expect_tx.shared::cta.b64 _, [%0], %1;"
                     :: "r"(mb), "r"(TILE_BYTES) : "memory");
    }
    __syncthreads();

    // Read phase: 24 bulk copies of 1 KB each (contiguous per (b,t) slice)
    if (tid < T_IN) {
        const float* src = x + (size_t)(b * T_IN + tid) * IN_T_STRIDE + chunk * CHUNK;
        const uint32_t dst = smem_u32(&sm.tile[tid][0]);
        asm volatile(
            "cp.async.bulk.shared::cta.global.mbarrier::complete_tx::bytes "
            "[%0], [%1], %2, [%3];"
            :: "r"(dst), "l"(src), "r"(CHUNK * 4), "r"(mb) : "memory");
    }

    // Wait for the full tile
    {
        uint32_t done;
        do {
            asm volatile(
                "{\n\t.reg .pred p;\n\t"
                "mbarrier.try_wait.parity.acquire.cta.shared::cta.b64 p, [%1], %2;\n\t"
                "selp.b32 %0, 1, 0, p;\n\t}"
                : "=r"(done) : "r"(mb), "r"(0) : "memory");
        } while (!done);
    }

    // Compile-time constants
    float lam23 = 1.0f;
    #pragma unroll
    for (int i = 0; i < 23; i++) lam23 *= LAM;
    const float base = lam23 / 24.0f;
    const float Kc   = MU_ * lam23;

    const int ml = tid * 2;   // local mn pair

    float va[T_IN], vb[T_IN];
    #pragma unroll
    for (int t = 0; t < T_IN; t++) {
        const float2 vv = *(const float2*)&sm.tile[t][ml];
        va[t] = vv.x; vb[t] = vv.y;
    }

    float Bsa = 0.f, Ra = 0.f, Bsb = 0.f, Rb = 0.f;
    #pragma unroll
    for (int t = 0; t < T_IN; t++) {
        Bsa += va[t]; Bsb += vb[t];
        if (t < T_IN - 1) {
            Ra = fmaf(LAM, Ra, MU_ * va[t]);
            Rb = fmaf(LAM, Rb, MU_ * vb[t]);
        }
    }
    float v23a = va[T_IN - 1], v23b = vb[T_IN - 1];

    // Compute all outputs into smem staging (no gmem writes yet)
    #pragma unroll
    for (int s = 0; s < T_OUT; s++) {
        const float pa = fmaf(base, Bsa, Ra);
        const float pb = fmaf(base, Bsb, Rb);
        float2 o; o.x = pa; o.y = pb;
        *(float2*)&sm.outb[s][ml] = o;

        const float xa = va[s], xb = vb[s];
        Bsa = (Bsa - xa) + pa;
        Bsb = (Bsb - xb) + pb;
        Ra = fmaf(LAM, Ra, fmaf(MU_, v23a, -Kc * xa));
        Rb = fmaf(LAM, Rb, fmaf(MU_, v23b, -Kc * xb));
        v23a = pa; v23b = pb;
    }

    __syncthreads();

    // Write phase: 12 bulk stores of 1 KB each (TMA path, burst writes)
    if (tid < T_OUT) {
        asm volatile("fence.proxy.async.shared::cta;" ::: "memory");
        float* dst = out + (size_t)b * OUT_B_STRIDE + (size_t)tid * MN + chunk * CHUNK;
        const uint32_t src = smem_u32(&sm.outb[tid][0]);
        asm volatile(
            "cp.async.bulk.global.shared::cta.bulk_group [%0], [%1], %2;"
            :: "l"(dst), "r"(src), "r"(CHUNK * 4) : "memory");
        asm volatile("cp.async.bulk.commit_group;" ::: "memory");
        asm volatile("cp.async.bulk.wait_group 0;" ::: "memory");
    }
}

extern "C" void kernel_launch(void* const* d_in, const int* in_sizes, int n_in,
                              void* d_out, int out_size)
{
    const float* x = (const float*)d_in[0];
    float* out = (float*)d_out;
    movavg_kernel<<<B * NCHUNK, THREADS>>>(x, out);   // 1024 CTAs
}

// round 14
// speedup vs baseline: 1.2741x; 1.2741x over previous
#include <cuda_runtime.h>
#include <cstdint>

// Problem constants
#define B      32
#define T_IN   24
#define T_OUT  12
#define D      10
#define M      64
#define N      128
#define MN     (M * N)                 // 8192
#define IN_T_STRIDE  (D * MN)          // 81920 floats between t slices
#define IN_B_STRIDE  (T_IN * IN_T_STRIDE)
#define OUT_B_STRIDE (T_OUT * MN)
#define MU_    0.08f
#define LAM    0.92f

#define CHUNK      256                 // mn per CTA
#define NCHUNK     (MN / CHUNK)        // 32
#define THREADS    128                 // 2 series per thread (float2)
#define TILE_BYTES (T_IN * CHUNK * 4)  // 24 KB

struct __align__(128) Smem {
    float tile[T_IN][CHUNK];
    alignas(8) uint64_t mbar;
};

__device__ __forceinline__ uint32_t smem_u32(const void* p) {
    return (uint32_t)__cvta_generic_to_shared(p);
}

__global__ __launch_bounds__(THREADS)
void movavg_kernel(const float* __restrict__ x, float* __restrict__ out)
{
    __shared__ Smem sm;

    const int bid   = blockIdx.x;
    const int b     = bid >> 5;          // / NCHUNK
    const int chunk = bid & (NCHUNK - 1);
    const int tid   = threadIdx.x;

    const uint32_t mb = smem_u32(&sm.mbar);

    if (tid == 0) {
        asm volatile("mbarrier.init.shared::cta.b64 [%0], %1;" :: "r"(mb), "r"(1));
        asm volatile("mbarrier.arrive.expect_tx.shared::cta.b64 _, [%0], %1;"
                     :: "r"(mb), "r"(TILE_BYTES) : "memory");
    }
    __syncthreads();

    // 24 bulk copies of 1 KB each (contiguous per (b,t) slice)
    if (tid < T_IN) {
        const float* src = x + (size_t)(b * T_IN + tid) * IN_T_STRIDE + chunk * CHUNK;
        const uint32_t dst = smem_u32(&sm.tile[tid][0]);
        asm volatile(
            "cp.async.bulk.shared::cta.global.mbarrier::complete_tx::bytes "
            "[%0], [%1], %2, [%3];"
            :: "r"(dst), "l"(src), "r"(CHUNK * 4), "r"(mb) : "memory");
    }

    // All threads wait for the full tile
    {
        uint32_t done;
        do {
            asm volatile(
                "{\n\t.reg .pred p;\n\t"
                "mbarrier.try_wait.parity.acquire.cta.shared::cta.b64 p, [%1], %2;\n\t"
                "selp.b32 %0, 1, 0, p;\n\t}"
                : "=r"(done) : "r"(mb), "r"(0) : "memory");
        } while (!done);
    }

    // Compile-time constants
    float lam23 = 1.0f;
    #pragma unroll
    for (int i = 0; i < 23; i++) lam23 *= LAM;
    const float base = lam23 / 24.0f;
    const float Kc   = MU_ * lam23;

    const int ml = tid * 2;   // local mn pair

    // Read the 24-sample window for 2 series from smem (conflict-free)
    float va[T_IN], vb[T_IN];
    #pragma unroll
    for (int t = 0; t < T_IN; t++) {
        const float2 vv = *(const float2*)&sm.tile[t][ml];
        va[t] = vv.x; vb[t] = vv.y;
    }

    // Bs = window sum; R = truncated EMA
    float Bsa = 0.f, Ra = 0.f, Bsb = 0.f, Rb = 0.f;
    #pragma unroll
    for (int t = 0; t < T_IN; t++) {
        Bsa += va[t]; Bsb += vb[t];
        if (t < T_IN - 1) {
            Ra = fmaf(LAM, Ra, MU_ * va[t]);
            Rb = fmaf(LAM, Rb, MU_ * vb[t]);
        }
    }
    float v23a = va[T_IN - 1], v23b = vb[T_IN - 1];

    float* __restrict__ yout = out + (size_t)b * OUT_B_STRIDE + chunk * CHUNK + ml;

    #pragma unroll
    for (int s = 0; s < T_OUT; s++) {
        const float pa = fmaf(base, Bsa, Ra);
        const float pb = fmaf(base, Bsb, Rb);
        float2 o; o.x = pa; o.y = pb;
        __stcs((float2*)(yout + (size_t)s * MN), o);   // streaming store

        const float xa = va[s], xb = vb[s];
        Bsa = (Bsa - xa) + pa;
        Bsb = (Bsb - xb) + pb;
        Ra = fmaf(LAM, Ra, fmaf(MU_, v23a, -Kc * xa));
        Rb = fmaf(LAM, Rb, fmaf(MU_, v23b, -Kc * xb));
        v23a = pa; v23b = pb;
    }
}

extern "C" void kernel_launch(void* const* d_in, const int* in_sizes, int n_in,
                              void* d_out, int out_size)
{
    const float* x = (const float*)d_in[0];
    float* out = (float*)d_out;
    movavg_kernel<<<B * NCHUNK, THREADS>>>(x, out);   // 1024 CTAs
}